// round 5
// baseline (speedup 1.0000x reference)
#include <cuda_runtime.h>
#include <cuda_fp16.h>
#include <cuda_bf16.h>

#define NN 50000
#define EE 800000
#define F1 128
#define F2 256   // HEADS*HID
#define HEADS 16
#define HID 16
#define OUTC 64
#define NEG_SLOPE 0.2f
#define EPSV 1e-16f
#define SCAN_BLK 49

// ---------------- scratch ----------------------------------------------------
__device__ __half g_w1h[F1 * F2];
__device__ __half g_w2h[F2 * OUTC];
__device__ __half g_h1h[(size_t)NN * F2];    // layer-1 features (half)
__device__ __half g_out1h[(size_t)NN * F2];  // layer-1 output (half)
__device__ __half g_h2h[(size_t)NN * OUTC];  // layer-2 features (half)
__device__ float  g_as1[(size_t)NN * HEADS];
__device__ float  g_ad1[(size_t)NN * HEADS];
__device__ float  g_as2[NN];
__device__ float  g_ad2[NN];
__device__ int    g_cnt[NN];
__device__ int    g_cur[NN];
__device__ int    g_off[NN + 1];
__device__ int    g_esrc[EE];
__device__ int    g_bsum[64];
__device__ int    g_eflag;

// ---------------- helpers -----------------------------------------------------
__device__ __forceinline__ float lrelu(float e) { return e > 0.f ? e : NEG_SLOPE * e; }

__device__ __forceinline__ void hmma16816(float* d, const unsigned* a, const unsigned* b) {
    asm volatile(
        "mma.sync.aligned.m16n8k16.row.col.f32.f16.f16.f32 "
        "{%0,%1,%2,%3}, {%4,%5,%6,%7}, {%8,%9}, {%0,%1,%2,%3};"
        : "+f"(d[0]), "+f"(d[1]), "+f"(d[2]), "+f"(d[3])
        : "r"(a[0]), "r"(a[1]), "r"(a[2]), "r"(a[3]), "r"(b[0]), "r"(b[1]));
}

// ---------------- weights convert (both W1 and W2, one launch) ------------------
__global__ void wconv_kernel(const float* __restrict__ W1, const float* __restrict__ W2) {
    int i = blockIdx.x * blockDim.x + threadIdx.x;
    const int n1 = F1 * F2 / 4;             // 8192 float4
    const int n2 = F2 * OUTC / 4;           // 4096 float4
    if (i < n1) {
        float4 v = ((const float4*)W1)[i];
        __half2 p0 = __floats2half2_rn(v.x, v.y);
        __half2 p1 = __floats2half2_rn(v.z, v.w);
        uint2 u; u.x = *(unsigned*)&p0; u.y = *(unsigned*)&p1;
        ((uint2*)g_w1h)[i] = u;
    } else if (i < n1 + n2) {
        int j = i - n1;
        float4 v = ((const float4*)W2)[j];
        __half2 p0 = __floats2half2_rn(v.x, v.y);
        __half2 p1 = __floats2half2_rn(v.z, v.w);
        uint2 u; u.x = *(unsigned*)&p0; u.y = *(unsigned*)&p1;
        ((uint2*)g_w2h)[j] = u;
    }
}

// ---------------- init + CSR build ----------------------------------------------
__global__ void init_kernel(const void* ei) {
    int i = blockIdx.x * blockDim.x + threadIdx.x;
    if (i < NN) { g_cnt[i] = 0; g_cur[i] = 0; }
    if (blockIdx.x == 0) {
        __shared__ int nz;
        if (threadIdx.x == 0) nz = 0;
        __syncthreads();
        const int* w = (const int*)ei;
        int any = 0;
        for (int j = threadIdx.x; j < 512; j += blockDim.x)
            if (w[2 * j + 1] != 0) any = 1;
        if (any) atomicOr(&nz, 1);
        __syncthreads();
        if (threadIdx.x == 0) g_eflag = nz ? 1 : 0;
    }
}

__global__ void hist_kernel(const void* ei) {
    int i = (blockIdx.x * blockDim.x + threadIdx.x) * 2;
    if (i >= EE) return;
    int d0, d1;
    if (g_eflag) {
        const int* p = (const int*)ei;
        int2 d2 = *(const int2*)&p[EE + i];
        d0 = d2.x; d1 = d2.y;
    } else {
        const long long* p = (const long long*)ei;
        longlong2 d2 = *(const longlong2*)&p[EE + i];
        d0 = (int)d2.x; d1 = (int)d2.y;
    }
    atomicAdd(&g_cnt[d0], 1);
    atomicAdd(&g_cnt[d1], 1);
}

__global__ void scanA_kernel() {
    __shared__ int wsum[32];
    int i = blockIdx.x * 1024 + threadIdx.x;
    int lane = threadIdx.x & 31, wid = threadIdx.x >> 5;
    int x = (i < NN) ? g_cnt[i] : 0;
    int incl = x;
#pragma unroll
    for (int d = 1; d < 32; d <<= 1) {
        int t = __shfl_up_sync(0xffffffffu, incl, d);
        if (lane >= d) incl += t;
    }
    if (lane == 31) wsum[wid] = incl;
    __syncthreads();
    if (wid == 0) {
        int y = wsum[lane];
#pragma unroll
        for (int d = 1; d < 32; d <<= 1) {
            int t = __shfl_up_sync(0xffffffffu, y, d);
            if (lane >= d) y += t;
        }
        wsum[lane] = y;
    }
    __syncthreads();
    if (wid > 0) incl += wsum[wid - 1];
    if (i < NN) g_off[i + 1] = incl;
    if (threadIdx.x == 1023) g_bsum[blockIdx.x] = incl;
}

// merged scanB+scanC: each block computes its own block-prefix (49 adds)
__global__ void scanC_kernel() {
    __shared__ int base;
    if (threadIdx.x == 0) {
        int s = 0;
        for (int j = 0; j < blockIdx.x; j++) s += g_bsum[j];
        base = s;
    }
    __syncthreads();
    int i = blockIdx.x * 1024 + threadIdx.x;
    if (i < NN) g_off[i + 1] += base;
    if (i == 0) g_off[0] = 0;
}

__global__ void scatter_kernel(const void* ei) {
    int i = (blockIdx.x * blockDim.x + threadIdx.x) * 2;
    if (i >= EE) return;
    int s0, s1, d0, d1;
    if (g_eflag) {
        const int* p = (const int*)ei;
        int2 s2 = *(const int2*)&p[i];
        int2 d2 = *(const int2*)&p[EE + i];
        s0 = s2.x; s1 = s2.y; d0 = d2.x; d1 = d2.y;
    } else {
        const long long* p = (const long long*)ei;
        longlong2 s2 = *(const longlong2*)&p[i];
        longlong2 d2 = *(const longlong2*)&p[EE + i];
        s0 = (int)s2.x; s1 = (int)s2.y; d0 = (int)d2.x; d1 = (int)d2.y;
    }
    int p0 = g_off[d0] + atomicAdd(&g_cur[d0], 1);
    g_esrc[p0] = s0;
    int p1 = g_off[d1] + atomicAdd(&g_cur[d1], 1);
    g_esrc[p1] = s1;
}

// ---------------- HMMA GEMM + fused alpha dots ----------------------------------
// Block tile 128x64, 8 warps (wm=wid%4 rows, wn=wid/4 cols), K-stage 64.
// AFLOAT: A is fp32, converted to half while staging smem.
template <int KIN, int KOUT, bool L1HEADS, bool AFLOAT>
__global__ void gemm_hmma(const void* __restrict__ Av, const __half* __restrict__ B,
                          __half* __restrict__ C,
                          const float* __restrict__ avs, const float* __restrict__ avd,
                          float* __restrict__ as_out, float* __restrict__ ad_out,
                          int M) {
    __shared__ __half As[128][72];
    __shared__ __half Bst[64][72];
    __shared__ float sAs[128], sAd[128];

    int tid = threadIdx.x;                 // 256
    int wid = tid >> 5, lane = tid & 31;
    int wm = wid & 3, wn = wid >> 2;
    int row0 = blockIdx.y * 128, col0 = blockIdx.x * 64;
    int lr = lane >> 2;                    // 0..7
    int lc = lane & 3;                     // 0..3

    float d[2][4][4];
#pragma unroll
    for (int a = 0; a < 2; a++)
#pragma unroll
        for (int b = 0; b < 4; b++)
#pragma unroll
            for (int c = 0; c < 4; c++) d[a][b][c] = 0.f;

    for (int k0 = 0; k0 < KIN; k0 += 64) {
        if (AFLOAT) {
            const float* A = (const float*)Av;
#pragma unroll
            for (int l = 0; l < 8; l++) {
                int idx = tid + l * 256;          // 0..2047 = 128 rows x 16 chunks(4 floats)
                int r = idx >> 4, c4 = idx & 15;
                int gr = row0 + r;
                float4 v = make_float4(0.f, 0.f, 0.f, 0.f);
                if (gr < M) v = *(const float4*)&A[(size_t)gr * KIN + k0 + c4 * 4];
                __half2 p0 = __floats2half2_rn(v.x, v.y);
                __half2 p1 = __floats2half2_rn(v.z, v.w);
                uint2 u; u.x = *(unsigned*)&p0; u.y = *(unsigned*)&p1;
                *(uint2*)&As[r][c4 * 4] = u;
            }
        } else {
            const __half* A = (const __half*)Av;
#pragma unroll
            for (int l = 0; l < 4; l++) {
                int idx = tid + l * 256;          // 0..1023 = 128 rows x 8 chunks(8 halfs)
                int r = idx >> 3, c8 = idx & 7;
                int gr = row0 + r;
                float4 v = make_float4(0.f, 0.f, 0.f, 0.f);
                if (gr < M) v = *(const float4*)&A[(size_t)gr * KIN + k0 + c8 * 8];
                *(float4*)&As[r][c8 * 8] = v;
            }
        }
#pragma unroll
        for (int l = 0; l < 2; l++) {
            int idx = tid + l * 256;              // 0..511 = 64 k-rows x 8 n-chunks
            int kr = idx >> 3, n8 = idx & 7;
            float4 v = *(const float4*)&B[(size_t)(k0 + kr) * KOUT + col0 + n8 * 8];
            const __half* hv = (const __half*)&v;
#pragma unroll
            for (int j = 0; j < 8; j++) Bst[n8 * 8 + j][kr] = hv[j];
        }
        __syncthreads();

#pragma unroll
        for (int kk = 0; kk < 4; kk++) {
            int kb = kk * 16;
            unsigned afr[2][4], bfr[4][2];
#pragma unroll
            for (int mt = 0; mt < 2; mt++) {
                int r = wm * 32 + mt * 16 + lr;
                afr[mt][0] = *(const unsigned*)&As[r][kb + lc * 2];
                afr[mt][1] = *(const unsigned*)&As[r + 8][kb + lc * 2];
                afr[mt][2] = *(const unsigned*)&As[r][kb + lc * 2 + 8];
                afr[mt][3] = *(const unsigned*)&As[r + 8][kb + lc * 2 + 8];
            }
#pragma unroll
            for (int nt = 0; nt < 4; nt++) {
                int n = wn * 32 + nt * 8 + lr;
                bfr[nt][0] = *(const unsigned*)&Bst[n][kb + lc * 2];
                bfr[nt][1] = *(const unsigned*)&Bst[n][kb + lc * 2 + 8];
            }
#pragma unroll
            for (int mt = 0; mt < 2; mt++)
#pragma unroll
                for (int nt = 0; nt < 4; nt++)
                    hmma16816(d[mt][nt], afr[mt], bfr[nt]);
        }
        __syncthreads();
    }

    // store C (half)
#pragma unroll
    for (int mt = 0; mt < 2; mt++) {
        int gr0 = row0 + wm * 32 + mt * 16 + lr;
#pragma unroll
        for (int nt = 0; nt < 4; nt++) {
            int gc = col0 + wn * 32 + nt * 8 + lc * 2;
            if (gr0 < M) {
                __half2 p = __floats2half2_rn(d[mt][nt][0], d[mt][nt][1]);
                *(unsigned*)&C[(size_t)gr0 * KOUT + gc] = *(unsigned*)&p;
            }
            if (gr0 + 8 < M) {
                __half2 p = __floats2half2_rn(d[mt][nt][2], d[mt][nt][3]);
                *(unsigned*)&C[(size_t)(gr0 + 8) * KOUT + gc] = *(unsigned*)&p;
            }
        }
    }

    // fused alpha dots
    if (L1HEADS) {
#pragma unroll
        for (int mt = 0; mt < 2; mt++) {
#pragma unroll
            for (int hp = 0; hp < 2; hp++) {
                int h = blockIdx.x * 4 + wn * 2 + hp;
                float psr = 0.f, pdr = 0.f, psr8 = 0.f, pdr8 = 0.f;
#pragma unroll
                for (int half_t = 0; half_t < 2; half_t++) {
                    int nt = hp * 2 + half_t;
                    int cl = half_t * 8 + lc * 2;
                    float w0s = avs[h * HID + cl], w1s = avs[h * HID + cl + 1];
                    float w0d = avd[h * HID + cl], w1d = avd[h * HID + cl + 1];
                    psr  += d[mt][nt][0] * w0s + d[mt][nt][1] * w1s;
                    pdr  += d[mt][nt][0] * w0d + d[mt][nt][1] * w1d;
                    psr8 += d[mt][nt][2] * w0s + d[mt][nt][3] * w1s;
                    pdr8 += d[mt][nt][2] * w0d + d[mt][nt][3] * w1d;
                }
#pragma unroll
                for (int dx = 1; dx <= 2; dx <<= 1) {
                    psr  += __shfl_xor_sync(0xffffffffu, psr, dx);
                    pdr  += __shfl_xor_sync(0xffffffffu, pdr, dx);
                    psr8 += __shfl_xor_sync(0xffffffffu, psr8, dx);
                    pdr8 += __shfl_xor_sync(0xffffffffu, pdr8, dx);
                }
                if (lc == 0) {
                    int gr = row0 + wm * 32 + mt * 16 + lr;
                    if (gr < M) {
                        as_out[(size_t)gr * HEADS + h] = psr;
                        ad_out[(size_t)gr * HEADS + h] = pdr;
                    }
                    if (gr + 8 < M) {
                        as_out[(size_t)(gr + 8) * HEADS + h] = psr8;
                        ad_out[(size_t)(gr + 8) * HEADS + h] = pdr8;
                    }
                }
            }
        }
    } else {
#pragma unroll
        for (int mt = 0; mt < 2; mt++) {
            float psr = 0.f, pdr = 0.f, psr8 = 0.f, pdr8 = 0.f;
#pragma unroll
            for (int nt = 0; nt < 4; nt++) {
                int cl = wn * 32 + nt * 8 + lc * 2;
                float w0s = avs[cl], w1s = avs[cl + 1];
                float w0d = avd[cl], w1d = avd[cl + 1];
                psr  += d[mt][nt][0] * w0s + d[mt][nt][1] * w1s;
                pdr  += d[mt][nt][0] * w0d + d[mt][nt][1] * w1d;
                psr8 += d[mt][nt][2] * w0s + d[mt][nt][3] * w1s;
                pdr8 += d[mt][nt][2] * w0d + d[mt][nt][3] * w1d;
            }
#pragma unroll
            for (int dx = 1; dx <= 2; dx <<= 1) {
                psr  += __shfl_xor_sync(0xffffffffu, psr, dx);
                pdr  += __shfl_xor_sync(0xffffffffu, pdr, dx);
                psr8 += __shfl_xor_sync(0xffffffffu, psr8, dx);
                pdr8 += __shfl_xor_sync(0xffffffffu, pdr8, dx);
            }
            if (lc == 0 && wn == 0) {
                int lrow = wm * 32 + mt * 16 + lr;
                sAs[lrow] = psr;  sAd[lrow] = pdr;
                sAs[lrow + 8] = psr8; sAd[lrow + 8] = pdr8;
            }
            __syncthreads();
            if (lc == 0 && wn == 1) {
                int lrow = wm * 32 + mt * 16 + lr;
                int gr = row0 + lrow;
                if (gr < M) {
                    as_out[gr] = sAs[lrow] + psr;
                    ad_out[gr] = sAd[lrow] + pdr;
                }
                if (gr + 8 < M) {
                    as_out[gr + 8] = sAs[lrow + 8] + psr8;
                    ad_out[gr + 8] = sAd[lrow + 8] + pdr8;
                }
            }
            __syncthreads();
        }
    }
}

// ---------------- layer-1 aggregation (warp/dst, 4x unrolled) -------------------
__device__ __forceinline__ void agg1_edge(int s, int h, float adh, int srcl, int lane,
                                          float& denom, float* acc) {
    float ex = __expf(lrelu(__ldg(&g_as1[(size_t)s * HEADS + h]) + adh));
    denom += ex;
    float em = __shfl_sync(0xffffffffu, ex, srcl);
    float4 raw = __ldg((const float4*)&g_h1h[(size_t)s * F2 + lane * 8]);
    const __half2* hp = (const __half2*)&raw;
#pragma unroll
    for (int j = 0; j < 4; j++) {
        float2 v = __half22float2(hp[j]);
        acc[j * 2 + 0] += v.x * em;
        acc[j * 2 + 1] += v.y * em;
    }
}

__global__ void agg1_kernel(const float* __restrict__ b1) {
    int w = (blockIdx.x * blockDim.x + threadIdx.x) >> 5;
    int lane = threadIdx.x & 31;
    if (w >= NN) return;
    int dst = w;
    int beg = g_off[dst], end = g_off[dst + 1];
    int h = lane & 15;
    float adh = g_ad1[(size_t)dst * HEADS + h];
    float exs = __expf(lrelu(g_as1[(size_t)dst * HEADS + h] + adh));
    float denom = exs;
    int srcl = lane >> 1;
    float exm = __shfl_sync(0xffffffffu, exs, srcl);

    float acc[8];
    {
        float4 raw = __ldg((const float4*)&g_h1h[(size_t)dst * F2 + lane * 8]);
        const __half2* hp = (const __half2*)&raw;
#pragma unroll
        for (int j = 0; j < 4; j++) {
            float2 v = __half22float2(hp[j]);
            acc[j * 2 + 0] = v.x * exm;
            acc[j * 2 + 1] = v.y * exm;
        }
    }

    int i = beg;
    for (; i + 4 <= end; i += 4) {
        int s0 = g_esrc[i], s1 = g_esrc[i + 1], s2 = g_esrc[i + 2], s3 = g_esrc[i + 3];
        float l0 = __ldg(&g_as1[(size_t)s0 * HEADS + h]);
        float l1 = __ldg(&g_as1[(size_t)s1 * HEADS + h]);
        float l2 = __ldg(&g_as1[(size_t)s2 * HEADS + h]);
        float l3 = __ldg(&g_as1[(size_t)s3 * HEADS + h]);
        float e0 = __expf(lrelu(l0 + adh));
        float e1 = __expf(lrelu(l1 + adh));
        float e2 = __expf(lrelu(l2 + adh));
        float e3 = __expf(lrelu(l3 + adh));
        denom += e0 + e1 + e2 + e3;
        float m0 = __shfl_sync(0xffffffffu, e0, srcl);
        float m1 = __shfl_sync(0xffffffffu, e1, srcl);
        float m2 = __shfl_sync(0xffffffffu, e2, srcl);
        float m3 = __shfl_sync(0xffffffffu, e3, srcl);
        float4 r0 = __ldg((const float4*)&g_h1h[(size_t)s0 * F2 + lane * 8]);
        float4 r1 = __ldg((const float4*)&g_h1h[(size_t)s1 * F2 + lane * 8]);
        float4 r2 = __ldg((const float4*)&g_h1h[(size_t)s2 * F2 + lane * 8]);
        float4 r3 = __ldg((const float4*)&g_h1h[(size_t)s3 * F2 + lane * 8]);
        const __half2 *p0 = (const __half2*)&r0, *p1 = (const __half2*)&r1;
        const __half2 *p2 = (const __half2*)&r2, *p3 = (const __half2*)&r3;
#pragma unroll
        for (int j = 0; j < 4; j++) {
            float2 v0 = __half22float2(p0[j]);
            float2 v1 = __half22float2(p1[j]);
            float2 v2 = __half22float2(p2[j]);
            float2 v3 = __half22float2(p3[j]);
            acc[j * 2 + 0] += v0.x * m0 + v1.x * m1 + v2.x * m2 + v3.x * m3;
            acc[j * 2 + 1] += v0.y * m0 + v1.y * m1 + v2.y * m2 + v3.y * m3;
        }
    }
    for (; i < end; i++) agg1_edge(g_esrc[i], h, adh, srcl, lane, denom, acc);

    float den = __shfl_sync(0xffffffffu, denom, srcl) + EPSV;
    float inv = 1.0f / den;
    int ch0 = lane * 8;
    __half2 o[4];
#pragma unroll
    for (int j = 0; j < 4; j++)
        o[j] = __floats2half2_rn(acc[j * 2 + 0] * inv + b1[ch0 + j * 2 + 0],
                                 acc[j * 2 + 1] * inv + b1[ch0 + j * 2 + 1]);
    *(uint2*)&g_out1h[(size_t)dst * F2 + ch0] = *(uint2*)&o[0];
    *(uint2*)&g_out1h[(size_t)dst * F2 + ch0 + 4] = *(uint2*)&o[2];
}

// ---------------- layer-2 aggregation + sigmoid (4x unrolled) -------------------
__global__ void agg2_kernel(const float* __restrict__ b2, float* __restrict__ out) {
    int w = (blockIdx.x * blockDim.x + threadIdx.x) >> 5;
    int lane = threadIdx.x & 31;
    if (w >= NN) return;
    int dst = w;
    int beg = g_off[dst], end = g_off[dst + 1];
    float adw = g_ad2[dst];
    float exs = __expf(lrelu(g_as2[dst] + adw));
    float denom = exs;
    float2 v0i = __half22float2(__ldg((const __half2*)&g_h2h[(size_t)dst * OUTC + lane * 2]));
    float2 acc = make_float2(v0i.x * exs, v0i.y * exs);

    int i = beg;
    for (; i + 4 <= end; i += 4) {
        int s0 = g_esrc[i], s1 = g_esrc[i + 1], s2 = g_esrc[i + 2], s3 = g_esrc[i + 3];
        float e0 = __expf(lrelu(__ldg(&g_as2[s0]) + adw));
        float e1 = __expf(lrelu(__ldg(&g_as2[s1]) + adw));
        float e2 = __expf(lrelu(__ldg(&g_as2[s2]) + adw));
        float e3 = __expf(lrelu(__ldg(&g_as2[s3]) + adw));
        denom += e0 + e1 + e2 + e3;
        float2 v0 = __half22float2(__ldg((const __half2*)&g_h2h[(size_t)s0 * OUTC + lane * 2]));
        float2 v1 = __half22float2(__ldg((const __half2*)&g_h2h[(size_t)s1 * OUTC + lane * 2]));
        float2 v2 = __half22float2(__ldg((const __half2*)&g_h2h[(size_t)s2 * OUTC + lane * 2]));
        float2 v3 = __half22float2(__ldg((const __half2*)&g_h2h[(size_t)s3 * OUTC + lane * 2]));
        acc.x += v0.x * e0 + v1.x * e1 + v2.x * e2 + v3.x * e3;
        acc.y += v0.y * e0 + v1.y * e1 + v2.y * e2 + v3.y * e3;
    }
    for (; i < end; i++) {
        int s = g_esrc[i];
        float ex = __expf(lrelu(__ldg(&g_as2[s]) + adw));
        denom += ex;
        float2 sv = __half22float2(__ldg((const __half2*)&g_h2h[(size_t)s * OUTC + lane * 2]));
        acc.x += sv.x * ex; acc.y += sv.y * ex;
    }
    float inv = 1.0f / (denom + EPSV);
    float x0 = acc.x * inv + b2[lane * 2 + 0];
    float x1 = acc.y * inv + b2[lane * 2 + 1];
    float2 o = make_float2(1.0f / (1.0f + __expf(-x0)), 1.0f / (1.0f + __expf(-x1)));
    *(float2*)(out + (size_t)dst * OUTC + lane * 2) = o;
}

// ---------------- launcher -------------------------------------------------------
extern "C" void kernel_launch(void* const* d_in, const int* in_sizes, int n_in,
                              void* d_out, int out_size) {
    const float* x      = (const float*)d_in[0];
    const void*  ei     = d_in[1];
    const float* W1     = (const float*)d_in[2];
    const float* a_src1 = (const float*)d_in[3];
    const float* a_dst1 = (const float*)d_in[4];
    const float* b1     = (const float*)d_in[5];
    const float* W2     = (const float*)d_in[6];
    const float* a_src2 = (const float*)d_in[7];
    const float* a_dst2 = (const float*)d_in[8];
    const float* b2     = (const float*)d_in[9];
    float* out = (float*)d_out;

    __half *w1h, *w2h, *h1, *o1, *h2;
    float *as1, *ad1, *as2, *ad2;
    cudaGetSymbolAddress((void**)&w1h, g_w1h);
    cudaGetSymbolAddress((void**)&w2h, g_w2h);
    cudaGetSymbolAddress((void**)&h1, g_h1h);
    cudaGetSymbolAddress((void**)&o1, g_out1h);
    cudaGetSymbolAddress((void**)&h2, g_h2h);
    cudaGetSymbolAddress((void**)&as1, g_as1);
    cudaGetSymbolAddress((void**)&ad1, g_ad1);
    cudaGetSymbolAddress((void**)&as2, g_as2);
    cudaGetSymbolAddress((void**)&ad2, g_ad2);

    static cudaStream_t s_side = 0;
    static cudaEvent_t evF = 0, evJ = 0;
    if (!s_side) {
        cudaStreamCreateWithFlags(&s_side, cudaStreamNonBlocking);
        cudaEventCreateWithFlags(&evF, cudaEventDisableTiming);
        cudaEventCreateWithFlags(&evJ, cudaEventDisableTiming);
    }

    // fork: CSR build on side stream
    cudaEventRecord(evF, 0);
    cudaStreamWaitEvent(s_side, evF, 0);
    init_kernel<<<(NN + 255) / 256, 256, 0, s_side>>>(ei);
    hist_kernel<<<(EE / 2 + 255) / 256, 256, 0, s_side>>>(ei);
    scanA_kernel<<<SCAN_BLK, 1024, 0, s_side>>>();
    scanC_kernel<<<SCAN_BLK, 1024, 0, s_side>>>();
    scatter_kernel<<<(EE / 2 + 255) / 256, 256, 0, s_side>>>(ei);
    cudaEventRecord(evJ, s_side);

    // main stream: weight converts + GEMM1 (x converted in-kernel)
    wconv_kernel<<<(F1 * F2 / 4 + F2 * OUTC / 4 + 255) / 256, 256>>>(W1, W2);
    {
        dim3 grid(F2 / 64, (NN + 127) / 128);
        gemm_hmma<F1, F2, true, true><<<grid, 256>>>(x, w1h, h1, a_src1, a_dst1, as1, ad1, NN);
    }

    cudaStreamWaitEvent(0, evJ, 0);

    agg1_kernel<<<(NN * 32 + 255) / 256, 256>>>(b1);
    {
        dim3 grid(OUTC / 64, (NN + 127) / 128);
        gemm_hmma<F2, OUTC, false, false><<<grid, 256>>>(o1, w2h, h2, a_src2, a_dst2, as2, ad2, NN);
    }
    agg2_kernel<<<(NN * 32 + 255) / 256, 256>>>(b2, out);
}

// round 6
// speedup vs baseline: 1.0484x; 1.0484x over previous
#include <cuda_runtime.h>
#include <cuda_fp16.h>
#include <cuda_bf16.h>

#define NN 50000
#define EE 800000
#define F1 128
#define F2 256   // HEADS*HID
#define HEADS 16
#define HID 16
#define OUTC 64
#define NEG_SLOPE 0.2f
#define EPSV 1e-16f
#define SCAN_BLK 49

// ---------------- scratch ----------------------------------------------------
__device__ __half g_w1h[F1 * F2];
__device__ __half g_w2h[F2 * OUTC];
__device__ __half g_h1h[(size_t)NN * F2];    // layer-1 features (half)
__device__ __half g_out1h[(size_t)NN * F2];  // layer-1 output (half)
__device__ __half g_h2h[(size_t)NN * OUTC];  // layer-2 features (half)
__device__ float  g_as1[(size_t)NN * HEADS];
__device__ float  g_ad1[(size_t)NN * HEADS];
__device__ float  g_as2[NN];
__device__ float  g_ad2[NN];
__device__ int    g_cnt[NN];
__device__ int    g_off[NN + 1];
__device__ int    g_esrc[EE];
__device__ int    g_rank[EE];
__device__ int    g_bsum[64];
__device__ int    g_eflag;

// ---------------- helpers -----------------------------------------------------
__device__ __forceinline__ float lrelu(float e) { return e > 0.f ? e : NEG_SLOPE * e; }

__device__ __forceinline__ void hmma16816(float* d, const unsigned* a, const unsigned* b) {
    asm volatile(
        "mma.sync.aligned.m16n8k16.row.col.f32.f16.f16.f32 "
        "{%0,%1,%2,%3}, {%4,%5,%6,%7}, {%8,%9}, {%0,%1,%2,%3};"
        : "+f"(d[0]), "+f"(d[1]), "+f"(d[2]), "+f"(d[3])
        : "r"(a[0]), "r"(a[1]), "r"(a[2]), "r"(a[3]), "r"(b[0]), "r"(b[1]));
}

// ---------------- weights convert ------------------------------------------------
__global__ void wconv_kernel(const float* __restrict__ W1, const float* __restrict__ W2) {
    int i = blockIdx.x * blockDim.x + threadIdx.x;
    const int n1 = F1 * F2 / 4;
    const int n2 = F2 * OUTC / 4;
    if (i < n1) {
        float4 v = ((const float4*)W1)[i];
        __half2 p0 = __floats2half2_rn(v.x, v.y);
        __half2 p1 = __floats2half2_rn(v.z, v.w);
        uint2 u; u.x = *(unsigned*)&p0; u.y = *(unsigned*)&p1;
        ((uint2*)g_w1h)[i] = u;
    } else if (i < n1 + n2) {
        int j = i - n1;
        float4 v = ((const float4*)W2)[j];
        __half2 p0 = __floats2half2_rn(v.x, v.y);
        __half2 p1 = __floats2half2_rn(v.z, v.w);
        uint2 u; u.x = *(unsigned*)&p0; u.y = *(unsigned*)&p1;
        ((uint2*)g_w2h)[j] = u;
    }
}

// ---------------- dtype detect ----------------------------------------------------
__global__ void detect_kernel(const void* ei) {
    __shared__ int nz;
    if (threadIdx.x == 0) nz = 0;
    __syncthreads();
    const int* w = (const int*)ei;
    int any = 0;
    for (int j = threadIdx.x; j < 512; j += blockDim.x)
        if (w[2 * j + 1] != 0) any = 1;
    if (any) atomicOr(&nz, 1);
    __syncthreads();
    if (threadIdx.x == 0) g_eflag = nz ? 1 : 0;
}

// ---------------- hist (+rank) ------------------------------------------------------
__global__ void hist_kernel(const void* ei) {
    int i = (blockIdx.x * blockDim.x + threadIdx.x) * 2;
    if (i >= EE) return;
    int d0, d1;
    if (g_eflag) {
        const int* p = (const int*)ei;
        int2 d2 = *(const int2*)&p[EE + i];
        d0 = d2.x; d1 = d2.y;
    } else {
        const long long* p = (const long long*)ei;
        longlong2 d2 = *(const longlong2*)&p[EE + i];
        d0 = (int)d2.x; d1 = (int)d2.y;
    }
    g_rank[i]     = atomicAdd(&g_cnt[d0], 1);
    g_rank[i + 1] = atomicAdd(&g_cnt[d1], 1);
}

__global__ void scanA_kernel() {
    __shared__ int wsum[32];
    int i = blockIdx.x * 1024 + threadIdx.x;
    int lane = threadIdx.x & 31, wid = threadIdx.x >> 5;
    int x = (i < NN) ? g_cnt[i] : 0;
    int incl = x;
#pragma unroll
    for (int d = 1; d < 32; d <<= 1) {
        int t = __shfl_up_sync(0xffffffffu, incl, d);
        if (lane >= d) incl += t;
    }
    if (lane == 31) wsum[wid] = incl;
    __syncthreads();
    if (wid == 0) {
        int y = wsum[lane];
#pragma unroll
        for (int d = 1; d < 32; d <<= 1) {
            int t = __shfl_up_sync(0xffffffffu, y, d);
            if (lane >= d) y += t;
        }
        wsum[lane] = y;
    }
    __syncthreads();
    if (wid > 0) incl += wsum[wid - 1];
    if (i < NN) g_off[i + 1] = incl;
    if (threadIdx.x == 1023) g_bsum[blockIdx.x] = incl;
}

__global__ void scanC_kernel() {
    __shared__ int base;
    if (threadIdx.x == 0) {
        int s = 0;
        for (int j = 0; j < blockIdx.x; j++) s += g_bsum[j];
        base = s;
    }
    __syncthreads();
    int i = blockIdx.x * 1024 + threadIdx.x;
    if (i < NN) g_off[i + 1] += base;
    if (i == 0) g_off[0] = 0;
}

// scatter without atomics: pos = off[dst] + rank
__global__ void scatter_kernel(const void* ei) {
    int i = (blockIdx.x * blockDim.x + threadIdx.x) * 2;
    if (i >= EE) return;
    int s0, s1, d0, d1;
    if (g_eflag) {
        const int* p = (const int*)ei;
        int2 s2 = *(const int2*)&p[i];
        int2 d2 = *(const int2*)&p[EE + i];
        s0 = s2.x; s1 = s2.y; d0 = d2.x; d1 = d2.y;
    } else {
        const long long* p = (const long long*)ei;
        longlong2 s2 = *(const longlong2*)&p[i];
        longlong2 d2 = *(const longlong2*)&p[EE + i];
        s0 = (int)s2.x; s1 = (int)s2.y; d0 = (int)d2.x; d1 = (int)d2.y;
    }
    int2 r = *(const int2*)&g_rank[i];
    g_esrc[g_off[d0] + r.x] = s0;
    g_esrc[g_off[d1] + r.y] = s1;
}

// ---------------- HMMA GEMM + fused alpha dots ----------------------------------
template <int KIN, int KOUT, bool L1HEADS, bool AFLOAT>
__global__ void gemm_hmma(const void* __restrict__ Av, const __half* __restrict__ B,
                          __half* __restrict__ C,
                          const float* __restrict__ avs, const float* __restrict__ avd,
                          float* __restrict__ as_out, float* __restrict__ ad_out,
                          int M) {
    __shared__ __half As[128][72];
    __shared__ __half Bst[64][72];
    __shared__ float sAs[128], sAd[128];

    int tid = threadIdx.x;                 // 256
    int wid = tid >> 5, lane = tid & 31;
    int wm = wid & 3, wn = wid >> 2;
    int row0 = blockIdx.y * 128, col0 = blockIdx.x * 64;
    int lr = lane >> 2;
    int lc = lane & 3;

    float d[2][4][4];
#pragma unroll
    for (int a = 0; a < 2; a++)
#pragma unroll
        for (int b = 0; b < 4; b++)
#pragma unroll
            for (int c = 0; c < 4; c++) d[a][b][c] = 0.f;

    for (int k0 = 0; k0 < KIN; k0 += 64) {
        if (AFLOAT) {
            const float* A = (const float*)Av;
#pragma unroll
            for (int l = 0; l < 8; l++) {
                int idx = tid + l * 256;
                int r = idx >> 4, c4 = idx & 15;
                int gr = row0 + r;
                float4 v = make_float4(0.f, 0.f, 0.f, 0.f);
                if (gr < M) v = *(const float4*)&A[(size_t)gr * KIN + k0 + c4 * 4];
                __half2 p0 = __floats2half2_rn(v.x, v.y);
                __half2 p1 = __floats2half2_rn(v.z, v.w);
                uint2 u; u.x = *(unsigned*)&p0; u.y = *(unsigned*)&p1;
                *(uint2*)&As[r][c4 * 4] = u;
            }
        } else {
            const __half* A = (const __half*)Av;
#pragma unroll
            for (int l = 0; l < 4; l++) {
                int idx = tid + l * 256;
                int r = idx >> 3, c8 = idx & 7;
                int gr = row0 + r;
                float4 v = make_float4(0.f, 0.f, 0.f, 0.f);
                if (gr < M) v = *(const float4*)&A[(size_t)gr * KIN + k0 + c8 * 8];
                *(float4*)&As[r][c8 * 8] = v;
            }
        }
#pragma unroll
        for (int l = 0; l < 2; l++) {
            int idx = tid + l * 256;
            int kr = idx >> 3, n8 = idx & 7;
            float4 v = *(const float4*)&B[(size_t)(k0 + kr) * KOUT + col0 + n8 * 8];
            const __half* hv = (const __half*)&v;
#pragma unroll
            for (int j = 0; j < 8; j++) Bst[n8 * 8 + j][kr] = hv[j];
        }
        __syncthreads();

#pragma unroll
        for (int kk = 0; kk < 4; kk++) {
            int kb = kk * 16;
            unsigned afr[2][4], bfr[4][2];
#pragma unroll
            for (int mt = 0; mt < 2; mt++) {
                int r = wm * 32 + mt * 16 + lr;
                afr[mt][0] = *(const unsigned*)&As[r][kb + lc * 2];
                afr[mt][1] = *(const unsigned*)&As[r + 8][kb + lc * 2];
                afr[mt][2] = *(const unsigned*)&As[r][kb + lc * 2 + 8];
                afr[mt][3] = *(const unsigned*)&As[r + 8][kb + lc * 2 + 8];
            }
#pragma unroll
            for (int nt = 0; nt < 4; nt++) {
                int n = wn * 32 + nt * 8 + lr;
                bfr[nt][0] = *(const unsigned*)&Bst[n][kb + lc * 2];
                bfr[nt][1] = *(const unsigned*)&Bst[n][kb + lc * 2 + 8];
            }
#pragma unroll
            for (int mt = 0; mt < 2; mt++)
#pragma unroll
                for (int nt = 0; nt < 4; nt++)
                    hmma16816(d[mt][nt], afr[mt], bfr[nt]);
        }
        __syncthreads();
    }

#pragma unroll
    for (int mt = 0; mt < 2; mt++) {
        int gr0 = row0 + wm * 32 + mt * 16 + lr;
#pragma unroll
        for (int nt = 0; nt < 4; nt++) {
            int gc = col0 + wn * 32 + nt * 8 + lc * 2;
            if (gr0 < M) {
                __half2 p = __floats2half2_rn(d[mt][nt][0], d[mt][nt][1]);
                *(unsigned*)&C[(size_t)gr0 * KOUT + gc] = *(unsigned*)&p;
            }
            if (gr0 + 8 < M) {
                __half2 p = __floats2half2_rn(d[mt][nt][2], d[mt][nt][3]);
                *(unsigned*)&C[(size_t)(gr0 + 8) * KOUT + gc] = *(unsigned*)&p;
            }
        }
    }

    if (L1HEADS) {
#pragma unroll
        for (int mt = 0; mt < 2; mt++) {
#pragma unroll
            for (int hp = 0; hp < 2; hp++) {
                int h = blockIdx.x * 4 + wn * 2 + hp;
                float psr = 0.f, pdr = 0.f, psr8 = 0.f, pdr8 = 0.f;
#pragma unroll
                for (int half_t = 0; half_t < 2; half_t++) {
                    int nt = hp * 2 + half_t;
                    int cl = half_t * 8 + lc * 2;
                    float w0s = avs[h * HID + cl], w1s = avs[h * HID + cl + 1];
                    float w0d = avd[h * HID + cl], w1d = avd[h * HID + cl + 1];
                    psr  += d[mt][nt][0] * w0s + d[mt][nt][1] * w1s;
                    pdr  += d[mt][nt][0] * w0d + d[mt][nt][1] * w1d;
                    psr8 += d[mt][nt][2] * w0s + d[mt][nt][3] * w1s;
                    pdr8 += d[mt][nt][2] * w0d + d[mt][nt][3] * w1d;
                }
#pragma unroll
                for (int dx = 1; dx <= 2; dx <<= 1) {
                    psr  += __shfl_xor_sync(0xffffffffu, psr, dx);
                    pdr  += __shfl_xor_sync(0xffffffffu, pdr, dx);
                    psr8 += __shfl_xor_sync(0xffffffffu, psr8, dx);
                    pdr8 += __shfl_xor_sync(0xffffffffu, pdr8, dx);
                }
                if (lc == 0) {
                    int gr = row0 + wm * 32 + mt * 16 + lr;
                    if (gr < M) {
                        as_out[(size_t)gr * HEADS + h] = psr;
                        ad_out[(size_t)gr * HEADS + h] = pdr;
                    }
                    if (gr + 8 < M) {
                        as_out[(size_t)(gr + 8) * HEADS + h] = psr8;
                        ad_out[(size_t)(gr + 8) * HEADS + h] = pdr8;
                    }
                }
            }
        }
    } else {
#pragma unroll
        for (int mt = 0; mt < 2; mt++) {
            float psr = 0.f, pdr = 0.f, psr8 = 0.f, pdr8 = 0.f;
#pragma unroll
            for (int nt = 0; nt < 4; nt++) {
                int cl = wn * 32 + nt * 8 + lc * 2;
                float w0s = avs[cl], w1s = avs[cl + 1];
                float w0d = avd[cl], w1d = avd[cl + 1];
                psr  += d[mt][nt][0] * w0s + d[mt][nt][1] * w1s;
                pdr  += d[mt][nt][0] * w0d + d[mt][nt][1] * w1d;
                psr8 += d[mt][nt][2] * w0s + d[mt][nt][3] * w1s;
                pdr8 += d[mt][nt][2] * w0d + d[mt][nt][3] * w1d;
            }
#pragma unroll
            for (int dx = 1; dx <= 2; dx <<= 1) {
                psr  += __shfl_xor_sync(0xffffffffu, psr, dx);
                pdr  += __shfl_xor_sync(0xffffffffu, pdr, dx);
                psr8 += __shfl_xor_sync(0xffffffffu, psr8, dx);
                pdr8 += __shfl_xor_sync(0xffffffffu, pdr8, dx);
            }
            if (lc == 0 && wn == 0) {
                int lrow = wm * 32 + mt * 16 + lr;
                sAs[lrow] = psr;  sAd[lrow] = pdr;
                sAs[lrow + 8] = psr8; sAd[lrow + 8] = pdr8;
            }
            __syncthreads();
            if (lc == 0 && wn == 1) {
                int lrow = wm * 32 + mt * 16 + lr;
                int gr = row0 + lrow;
                if (gr < M) {
                    as_out[gr] = sAs[lrow] + psr;
                    ad_out[gr] = sAd[lrow] + pdr;
                }
                if (gr + 8 < M) {
                    as_out[gr + 8] = sAs[lrow + 8] + psr8;
                    ad_out[gr + 8] = sAd[lrow + 8] + pdr8;
                }
            }
            __syncthreads();
        }
    }
}

// ---------------- layer-1 aggregation: shuffle-free, lane-local head ------------
__global__ void agg1_kernel(const float* __restrict__ b1) {
    int w = (blockIdx.x * blockDim.x + threadIdx.x) >> 5;
    int lane = threadIdx.x & 31;
    if (w >= NN) return;
    int dst = w;
    int beg = g_off[dst], end = g_off[dst + 1];
    int hh = lane >> 1;   // head owning this lane's 8 channels

    float adh = __ldg(&g_ad1[(size_t)dst * HEADS + hh]);
    float exs = __expf(lrelu(__ldg(&g_as1[(size_t)dst * HEADS + hh]) + adh));
    float denom = exs;

    float acc[8];
    {
        float4 raw = __ldg((const float4*)&g_h1h[(size_t)dst * F2 + lane * 8]);
        const __half2* hp = (const __half2*)&raw;
#pragma unroll
        for (int j = 0; j < 4; j++) {
            float2 v = __half22float2(hp[j]);
            acc[j * 2 + 0] = v.x * exs;
            acc[j * 2 + 1] = v.y * exs;
        }
    }

    int i = beg;
    for (; i + 2 <= end; i += 2) {
        int s0 = g_esrc[i], s1 = g_esrc[i + 1];
        float l0 = __ldg(&g_as1[(size_t)s0 * HEADS + hh]);
        float l1 = __ldg(&g_as1[(size_t)s1 * HEADS + hh]);
        float4 r0 = __ldg((const float4*)&g_h1h[(size_t)s0 * F2 + lane * 8]);
        float4 r1 = __ldg((const float4*)&g_h1h[(size_t)s1 * F2 + lane * 8]);
        float e0 = __expf(lrelu(l0 + adh));
        float e1 = __expf(lrelu(l1 + adh));
        denom += e0 + e1;
        const __half2 *p0 = (const __half2*)&r0, *p1 = (const __half2*)&r1;
#pragma unroll
        for (int j = 0; j < 4; j++) {
            float2 v0 = __half22float2(p0[j]);
            float2 v1 = __half22float2(p1[j]);
            acc[j * 2 + 0] += v0.x * e0 + v1.x * e1;
            acc[j * 2 + 1] += v0.y * e0 + v1.y * e1;
        }
    }
    if (i < end) {
        int s = g_esrc[i];
        float ex = __expf(lrelu(__ldg(&g_as1[(size_t)s * HEADS + hh]) + adh));
        denom += ex;
        float4 raw = __ldg((const float4*)&g_h1h[(size_t)s * F2 + lane * 8]);
        const __half2* hp = (const __half2*)&raw;
#pragma unroll
        for (int j = 0; j < 4; j++) {
            float2 v = __half22float2(hp[j]);
            acc[j * 2 + 0] += v.x * ex;
            acc[j * 2 + 1] += v.y * ex;
        }
    }

    float inv = 1.0f / (denom + EPSV);
    int ch0 = lane * 8;
    __half2 o[4];
#pragma unroll
    for (int j = 0; j < 4; j++)
        o[j] = __floats2half2_rn(acc[j * 2 + 0] * inv + b1[ch0 + j * 2 + 0],
                                 acc[j * 2 + 1] * inv + b1[ch0 + j * 2 + 1]);
    *(uint2*)&g_out1h[(size_t)dst * F2 + ch0] = *(uint2*)&o[0];
    *(uint2*)&g_out1h[(size_t)dst * F2 + ch0 + 4] = *(uint2*)&o[2];
}

// ---------------- layer-2 aggregation + sigmoid ---------------------------------
__global__ void agg2_kernel(const float* __restrict__ b2, float* __restrict__ out) {
    int w = (blockIdx.x * blockDim.x + threadIdx.x) >> 5;
    int lane = threadIdx.x & 31;
    if (w >= NN) return;
    int dst = w;
    int beg = g_off[dst], end = g_off[dst + 1];
    float adw = g_ad2[dst];
    float exs = __expf(lrelu(g_as2[dst] + adw));
    float denom = exs;
    float2 v0i = __half22float2(__ldg((const __half2*)&g_h2h[(size_t)dst * OUTC + lane * 2]));
    float2 acc = make_float2(v0i.x * exs, v0i.y * exs);

    int i = beg;
    for (; i + 2 <= end; i += 2) {
        int s0 = g_esrc[i], s1 = g_esrc[i + 1];
        float l0 = __ldg(&g_as2[s0]);
        float l1 = __ldg(&g_as2[s1]);
        float2 v0 = __half22float2(__ldg((const __half2*)&g_h2h[(size_t)s0 * OUTC + lane * 2]));
        float2 v1 = __half22float2(__ldg((const __half2*)&g_h2h[(size_t)s1 * OUTC + lane * 2]));
        float e0 = __expf(lrelu(l0 + adw));
        float e1 = __expf(lrelu(l1 + adw));
        denom += e0 + e1;
        acc.x += v0.x * e0 + v1.x * e1;
        acc.y += v0.y * e0 + v1.y * e1;
    }
    if (i < end) {
        int s = g_esrc[i];
        float ex = __expf(lrelu(__ldg(&g_as2[s]) + adw));
        denom += ex;
        float2 sv = __half22float2(__ldg((const __half2*)&g_h2h[(size_t)s * OUTC + lane * 2]));
        acc.x += sv.x * ex; acc.y += sv.y * ex;
    }
    float inv = 1.0f / (denom + EPSV);
    float x0 = acc.x * inv + b2[lane * 2 + 0];
    float x1 = acc.y * inv + b2[lane * 2 + 1];
    float2 o = make_float2(1.0f / (1.0f + __expf(-x0)), 1.0f / (1.0f + __expf(-x1)));
    *(float2*)(out + (size_t)dst * OUTC + lane * 2) = o;
}

// ---------------- launcher -------------------------------------------------------
extern "C" void kernel_launch(void* const* d_in, const int* in_sizes, int n_in,
                              void* d_out, int out_size) {
    const float* x      = (const float*)d_in[0];
    const void*  ei     = d_in[1];
    const float* W1     = (const float*)d_in[2];
    const float* a_src1 = (const float*)d_in[3];
    const float* a_dst1 = (const float*)d_in[4];
    const float* b1     = (const float*)d_in[5];
    const float* W2     = (const float*)d_in[6];
    const float* a_src2 = (const float*)d_in[7];
    const float* a_dst2 = (const float*)d_in[8];
    const float* b2     = (const float*)d_in[9];
    float* out = (float*)d_out;

    __half *w1h, *w2h, *h1, *o1, *h2;
    float *as1, *ad1, *as2, *ad2;
    int* cntp;
    cudaGetSymbolAddress((void**)&w1h, g_w1h);
    cudaGetSymbolAddress((void**)&w2h, g_w2h);
    cudaGetSymbolAddress((void**)&h1, g_h1h);
    cudaGetSymbolAddress((void**)&o1, g_out1h);
    cudaGetSymbolAddress((void**)&h2, g_h2h);
    cudaGetSymbolAddress((void**)&as1, g_as1);
    cudaGetSymbolAddress((void**)&ad1, g_ad1);
    cudaGetSymbolAddress((void**)&as2, g_as2);
    cudaGetSymbolAddress((void**)&ad2, g_ad2);
    cudaGetSymbolAddress((void**)&cntp, g_cnt);

    static cudaStream_t s_side = 0;
    static cudaEvent_t evF = 0, evJ = 0;
    if (!s_side) {
        cudaStreamCreateWithFlags(&s_side, cudaStreamNonBlocking);
        cudaEventCreateWithFlags(&evF, cudaEventDisableTiming);
        cudaEventCreateWithFlags(&evJ, cudaEventDisableTiming);
    }

    // fork: CSR build on side stream
    cudaEventRecord(evF, 0);
    cudaStreamWaitEvent(s_side, evF, 0);
    cudaMemsetAsync(cntp, 0, NN * sizeof(int), s_side);
    detect_kernel<<<1, 256, 0, s_side>>>(ei);
    hist_kernel<<<(EE / 2 + 255) / 256, 256, 0, s_side>>>(ei);
    scanA_kernel<<<SCAN_BLK, 1024, 0, s_side>>>();
    scanC_kernel<<<SCAN_BLK, 1024, 0, s_side>>>();
    scatter_kernel<<<(EE / 2 + 255) / 256, 256, 0, s_side>>>(ei);
    cudaEventRecord(evJ, s_side);

    // main stream: weight converts + GEMM1 (x converted in-kernel)
    wconv_kernel<<<(F1 * F2 / 4 + F2 * OUTC / 4 + 255) / 256, 256>>>(W1, W2);
    {
        dim3 grid(F2 / 64, (NN + 127) / 128);
        gemm_hmma<F1, F2, true, true><<<grid, 256>>>(x, w1h, h1, a_src1, a_dst1, as1, ad1, NN);
    }

    cudaStreamWaitEvent(0, evJ, 0);

    agg1_kernel<<<(NN * 32 + 255) / 256, 256>>>(b1);
    {
        dim3 grid(OUTC / 64, (NN + 127) / 128);
        gemm_hmma<F2, OUTC, false, false><<<grid, 256>>>(o1, w2h, h2, a_src2, a_dst2, as2, ad2, NN);
    }
    agg2_kernel<<<(NN * 32 + 255) / 256, 256>>>(b2, out);
}